// round 1
// baseline (speedup 1.0000x reference)
#include <cuda_runtime.h>
#include <cuda_bf16.h>

#define BB 32
#define TT 128
#define UU 64
#define EE 512
#define VV 32000
#define NROWS (BB*TT)                 // 4096
#define OUT_SOFT 131072000LL          // NROWS * VV

// ---------------- device scratch (no allocations allowed) ----------------
__device__ float g_xz[NROWS * 256];                         // 4 MB
__device__ float g_seq[NROWS * UU];                         // 1 MB
__device__ __align__(16) __nv_bfloat16 g_feat[NROWS * 128]; // 1 MB
__device__ __align__(16) __nv_bfloat16 g_WdT[VV * 128];     // 8 MB (Wd transposed, bf16)
__device__ float g_S[NROWS];                                // softmax denominators

__device__ __forceinline__ float sigmoidf_(float x) { return 1.0f / (1.0f + __expf(-x)); }

// ---------------- Wd [128, 32000] f32 -> WdT [32000, 128] bf16 ----------------
__global__ void k_wdt(const float* __restrict__ Wd) {
    __shared__ __nv_bfloat16 ts[32][33];
    int nt = blockIdx.x * 32, kt = blockIdx.y * 32;
    int tx = threadIdx.x, ty = threadIdx.y;   // block (32, 8)
#pragma unroll
    for (int r = 0; r < 4; r++) {
        int kl = ty + r * 8;
        ts[kl][tx] = __float2bfloat16(Wd[(kt + kl) * VV + nt + tx]);
    }
    __syncthreads();
#pragma unroll
    for (int r = 0; r < 4; r++) {
        int nl = ty + r * 8;
        g_WdT[(nt + nl) * 128 + kt + tx] = ts[tx][nl];
    }
}

__global__ void k_zero() {
    int i = blockIdx.x * 256 + threadIdx.x;
    if (i < NROWS) g_S[i] = 0.f;
}

// ---------------- xz = emb[tok] @ Wx + b : [4096, 256] ----------------
__global__ __launch_bounds__(256) void k_embed(const int* __restrict__ tok,
                                               const float* __restrict__ emb,
                                               const float* __restrict__ Wx,
                                               const float* __restrict__ bias) {
    __shared__ float xs[64][36];   // [k_local][row], padded stride 36
    __shared__ int toks[32];
    int tid = threadIdx.x;
    int row0 = blockIdx.x * 32;
    if (tid < 32) toks[tid] = tok[row0 + tid];
    int jc = (tid & 63) * 4;       // 4 output cols
    int rb = (tid >> 6) * 8;       // 8 output rows
    float acc[8][4];
    float4 bv = *(const float4*)&bias[jc];
#pragma unroll
    for (int r = 0; r < 8; r++) { acc[r][0] = bv.x; acc[r][1] = bv.y; acc[r][2] = bv.z; acc[r][3] = bv.w; }
    for (int kc = 0; kc < 8; kc++) {
        __syncthreads();
#pragma unroll
        for (int i = 0; i < 8; i++) {
            int e = tid + i * 256; int r = e >> 6; int kk = e & 63;
            xs[kk][r] = emb[(long long)toks[r] * EE + kc * 64 + kk];
        }
        __syncthreads();
#pragma unroll 8
        for (int kk = 0; kk < 64; kk++) {
            float4 w  = *(const float4*)&Wx[(kc * 64 + kk) * 256 + jc];
            float4 x0 = *(const float4*)&xs[kk][rb];
            float4 x1 = *(const float4*)&xs[kk][rb + 4];
            float xv[8] = {x0.x, x0.y, x0.z, x0.w, x1.x, x1.y, x1.z, x1.w};
#pragma unroll
            for (int r = 0; r < 8; r++) {
                acc[r][0] += xv[r] * w.x; acc[r][1] += xv[r] * w.y;
                acc[r][2] += xv[r] * w.z; acc[r][3] += xv[r] * w.w;
            }
        }
    }
#pragma unroll
    for (int r = 0; r < 8; r++)
        *(float4*)&g_xz[(row0 + rb + r) * 256 + jc] = *(float4*)acc[r];
}

// ---------------- LSTM scan: 32 CTAs (one per batch), serial over T ----------------
__global__ __launch_bounds__(256) void k_lstm(const float* __restrict__ h0,
                                              const float* __restrict__ c0,
                                              const float* __restrict__ Wh,
                                              float* __restrict__ out) {
    int b = blockIdx.x, j = threadIdx.x;
    float wh[64];
#pragma unroll
    for (int k = 0; k < 64; k++) wh[k] = Wh[k * 256 + j];
    __shared__ __align__(16) float hsh[64];
    __shared__ float zb[256];
    if (j < 64) hsh[j] = h0[b * 64 + j];
    float creg = (j < 64) ? c0[b * 64 + j] : 0.f;
    __syncthreads();
    for (int t = 0; t < TT; t++) {
        float acc = g_xz[(b * TT + t) * 256 + j];
        float s[4] = {0.f, 0.f, 0.f, 0.f};
#pragma unroll
        for (int c = 0; c < 4; c++) {
#pragma unroll
            for (int q = 0; q < 4; q++) {
                float4 h4 = *(const float4*)&hsh[c * 16 + q * 4];
                s[c] += wh[c * 16 + q * 4 + 0] * h4.x + wh[c * 16 + q * 4 + 1] * h4.y
                      + wh[c * 16 + q * 4 + 2] * h4.z + wh[c * 16 + q * 4 + 3] * h4.w;
            }
        }
        acc += (s[0] + s[1]) + (s[2] + s[3]);
        zb[j] = acc;
        __syncthreads();
        if (j < 64) {
            float iv = sigmoidf_(zb[j]);
            float fv = sigmoidf_(zb[64 + j]);
            float gv = tanhf(zb[128 + j]);
            float ov = sigmoidf_(zb[192 + j]);
            creg = fv * creg + iv * gv;
            float hn = ov * tanhf(creg);
            hsh[j] = hn;
            g_seq[(b * TT + t) * UU + j] = hn;
        }
        __syncthreads();
    }
    if (j < 64) {
        out[OUT_SOFT + b * 64 + j] = hsh[j];          // hT
        out[OUT_SOFT + 2048 + b * 64 + j] = creg;     // cT
    }
}

// ---------------- attention + feat(bf16) ----------------
__global__ __launch_bounds__(128) void k_attn(const float* __restrict__ enc,
                                              const float* __restrict__ h0) {
    int t = blockIdx.x, b = blockIdx.y;
    int s = threadIdx.x;
    __shared__ __align__(16) float kv[64];
    __shared__ float pr[128];
    __shared__ float wred[4];
    if (s < 64) kv[s] = (t == 0) ? h0[b * 64 + s] : g_seq[(b * TT + t - 1) * UU + s];
    __syncthreads();
    const float* encb = enc + (long long)b * TT * UU;
    float sc = 0.f;
#pragma unroll
    for (int u4 = 0; u4 < 16; u4++) {
        float4 e4 = *(const float4*)&encb[s * UU + u4 * 4];
        float4 k4 = *(const float4*)&kv[u4 * 4];
        sc += e4.x * k4.x + e4.y * k4.y + e4.z * k4.z + e4.w * k4.w;
    }
    float m = sc;
#pragma unroll
    for (int o = 16; o > 0; o >>= 1) m = fmaxf(m, __shfl_xor_sync(0xffffffffu, m, o));
    if ((s & 31) == 0) wred[s >> 5] = m;
    __syncthreads();
    m = fmaxf(fmaxf(wred[0], wred[1]), fmaxf(wred[2], wred[3]));
    float ev = __expf(sc - m);
    float sm = ev;
#pragma unroll
    for (int o = 16; o > 0; o >>= 1) sm += __shfl_xor_sync(0xffffffffu, sm, o);
    __syncthreads();
    if ((s & 31) == 0) wred[s >> 5] = sm;
    __syncthreads();
    sm = wred[0] + wred[1] + wred[2] + wred[3];
    pr[s] = ev / sm;
    __syncthreads();
    if (s < 64) {
        float cx = 0.f;
#pragma unroll 8
        for (int q = 0; q < 128; q++) cx += pr[q] * encb[q * UU + s];
        int row = b * TT + t;
        g_feat[row * 128 + 64 + s] = __float2bfloat16(cx);
        g_feat[row * 128 + s]      = __float2bfloat16(g_seq[row * UU + s]);
    }
}

// ---------------- big GEMM: logits = feat[4096,128] @ Wd[128,32000] + bd ----------------
// Pass A (WRITE=0): S[row] += sum(exp(z));  Pass B (WRITE=1): out = exp(z)/S[row]
#define SMEM_GEMM (2 * 128 * 136 * 2 + 2 * 128 * 4)   // 70656 bytes

template <int WRITE>
__global__ __launch_bounds__(256, 2) void k_gemm(const float* __restrict__ bd,
                                                 float* __restrict__ out) {
    extern __shared__ __align__(16) char smem_raw[];
    __nv_bfloat16* Bs = (__nv_bfloat16*)smem_raw;       // [128 n][136 k]
    __nv_bfloat16* As = Bs + 128 * 136;                 // [128 m][136 k]
    float* bds = (float*)(As + 128 * 136);
    float* sSm = bds + 128;
    int tid = threadIdx.x;
    int nb = blockIdx.x * 128;

    // B tile resident across all M-tiles
#pragma unroll
    for (int i = 0; i < 8; i++) {
        int ch = tid + i * 256; int r = ch >> 4; int kc = (ch & 15) * 8;
        *(uint4*)&Bs[r * 136 + kc] = *(const uint4*)&g_WdT[(nb + r) * 128 + kc];
    }
    if (tid < 128) bds[tid] = bd[nb + tid];

    int w = tid >> 5, lane = tid & 31;
    int wm = (w & 3) * 32, wn = (w >> 2) * 64;
    int g = lane >> 2, qt = lane & 3;

    for (int mt = 0; mt < 32; mt++) {
        int mb = mt * 128;
        __syncthreads();
#pragma unroll
        for (int i = 0; i < 8; i++) {
            int ch = tid + i * 256; int r = ch >> 4; int kc = (ch & 15) * 8;
            *(uint4*)&As[r * 136 + kc] = *(const uint4*)&g_feat[(mb + r) * 128 + kc];
        }
        if (WRITE && tid < 128) sSm[tid] = g_S[mb + tid];
        __syncthreads();

        float acc[2][8][4];
#pragma unroll
        for (int mf = 0; mf < 2; mf++)
#pragma unroll
            for (int nf = 0; nf < 8; nf++)
#pragma unroll
                for (int q = 0; q < 4; q++) acc[mf][nf][q] = 0.f;

#pragma unroll
        for (int ks = 0; ks < 8; ks++) {
            int kk = ks * 16 + qt * 2;
            unsigned a[2][4];
#pragma unroll
            for (int mf = 0; mf < 2; mf++) {
                int rr = wm + mf * 16 + g;
                a[mf][0] = *(const unsigned*)&As[rr * 136 + kk];
                a[mf][1] = *(const unsigned*)&As[(rr + 8) * 136 + kk];
                a[mf][2] = *(const unsigned*)&As[rr * 136 + kk + 8];
                a[mf][3] = *(const unsigned*)&As[(rr + 8) * 136 + kk + 8];
            }
#pragma unroll
            for (int nf = 0; nf < 8; nf++) {
                int cc = wn + nf * 8 + g;
                unsigned b0 = *(const unsigned*)&Bs[cc * 136 + kk];
                unsigned b1 = *(const unsigned*)&Bs[cc * 136 + kk + 8];
#pragma unroll
                for (int mf = 0; mf < 2; mf++) {
                    asm volatile(
                        "mma.sync.aligned.m16n8k16.row.col.f32.bf16.bf16.f32 "
                        "{%0,%1,%2,%3}, {%4,%5,%6,%7}, {%8,%9}, {%0,%1,%2,%3};\n"
                        : "+f"(acc[mf][nf][0]), "+f"(acc[mf][nf][1]),
                          "+f"(acc[mf][nf][2]), "+f"(acc[mf][nf][3])
                        : "r"(a[mf][0]), "r"(a[mf][1]), "r"(a[mf][2]), "r"(a[mf][3]),
                          "r"(b0), "r"(b1));
                }
            }
        }

#pragma unroll
        for (int mf = 0; mf < 2; mf++) {
            int r0 = wm + mf * 16 + g;
            if (WRITE) {
                float is0 = 1.0f / sSm[r0];
                float is1 = 1.0f / sSm[r0 + 8];
                long long ro0 = (long long)(mb + r0) * VV + nb;
                long long ro1 = (long long)(mb + r0 + 8) * VV + nb;
#pragma unroll
                for (int nf = 0; nf < 8; nf++) {
                    int c0 = wn + nf * 8 + qt * 2;
                    float bd0 = bds[c0], bd1 = bds[c0 + 1];
                    float2 v0, v1;
                    v0.x = __expf(acc[mf][nf][0] + bd0) * is0;
                    v0.y = __expf(acc[mf][nf][1] + bd1) * is0;
                    v1.x = __expf(acc[mf][nf][2] + bd0) * is1;
                    v1.y = __expf(acc[mf][nf][3] + bd1) * is1;
                    *(float2*)&out[ro0 + c0] = v0;
                    *(float2*)&out[ro1 + c0] = v1;
                }
            } else {
                float rs0 = 0.f, rs1 = 0.f;
#pragma unroll
                for (int nf = 0; nf < 8; nf++) {
                    int c0 = wn + nf * 8 + qt * 2;
                    float bd0 = bds[c0], bd1 = bds[c0 + 1];
                    rs0 += __expf(acc[mf][nf][0] + bd0) + __expf(acc[mf][nf][1] + bd1);
                    rs1 += __expf(acc[mf][nf][2] + bd0) + __expf(acc[mf][nf][3] + bd1);
                }
                rs0 += __shfl_xor_sync(0xffffffffu, rs0, 1);
                rs0 += __shfl_xor_sync(0xffffffffu, rs0, 2);
                rs1 += __shfl_xor_sync(0xffffffffu, rs1, 1);
                rs1 += __shfl_xor_sync(0xffffffffu, rs1, 2);
                if (qt == 0) {
                    atomicAdd(&g_S[mb + r0], rs0);
                    atomicAdd(&g_S[mb + r0 + 8], rs1);
                }
            }
        }
    }
}

// ---------------- launch ----------------
extern "C" void kernel_launch(void* const* d_in, const int* in_sizes, int n_in,
                              void* d_out, int out_size) {
    (void)in_sizes; (void)n_in; (void)out_size;
    const float* enc  = (const float*)d_in[0];
    const int*   dec  = (const int*)d_in[1];
    const float* h0   = (const float*)d_in[2];
    const float* c0   = (const float*)d_in[3];
    const float* emb  = (const float*)d_in[4];
    const float* Wx   = (const float*)d_in[5];
    const float* Wh   = (const float*)d_in[6];
    const float* bias = (const float*)d_in[7];
    const float* Wd   = (const float*)d_in[8];
    const float* bd   = (const float*)d_in[9];
    float* out = (float*)d_out;

    cudaFuncSetAttribute(k_gemm<0>, cudaFuncAttributeMaxDynamicSharedMemorySize, SMEM_GEMM);
    cudaFuncSetAttribute(k_gemm<1>, cudaFuncAttributeMaxDynamicSharedMemorySize, SMEM_GEMM);

    k_wdt<<<dim3(1000, 4), dim3(32, 8)>>>(Wd);
    k_zero<<<16, 256>>>();
    k_embed<<<128, 256>>>(dec, emb, Wx, bias);
    k_lstm<<<32, 256>>>(h0, c0, Wh, out);
    k_attn<<<dim3(128, 32), 128>>>(enc, h0);
    k_gemm<0><<<250, 256, SMEM_GEMM>>>(bd, out);
    k_gemm<1><<<250, 256, SMEM_GEMM>>>(bd, out);
}

// round 2
// speedup vs baseline: 1.0660x; 1.0660x over previous
#include <cuda_runtime.h>
#include <cuda_bf16.h>
#include <cuda_fp16.h>

#define BB 32
#define TT 128
#define UU 64
#define EE 512
#define VV 32000
#define NROWS (BB*TT)                 // 4096
#define OUT_SOFT 131072000LL          // NROWS * VV

// ---------------- device scratch (no allocations allowed) ----------------
__device__ float g_xz[NROWS * 256];                         // 4 MB
__device__ float g_seq[NROWS * UU];                         // 1 MB
__device__ __align__(16) __nv_bfloat16 g_feat[NROWS * 128]; // 1 MB
__device__ __align__(16) __nv_bfloat16 g_WdT[VV * 128];     // 8 MB (Wd transposed, bf16)
__device__ __align__(8) __half g_E[NROWS * (long long)VV];  // 262 MB unnormalized exp cache
__device__ float g_S[NROWS];                                // softmax denominators

__device__ __forceinline__ float tanh_ap(float x) {
    float y; asm("tanh.approx.f32 %0, %1;" : "=f"(y) : "f"(x)); return y;
}
__device__ __forceinline__ float sigmoid_ap(float x) {
    return 0.5f * tanh_ap(0.5f * x) + 0.5f;
}

// ---------------- Wd [128, 32000] f32 -> WdT [32000, 128] bf16 ----------------
__global__ void k_wdt(const float* __restrict__ Wd) {
    __shared__ __nv_bfloat16 ts[32][33];
    int nt = blockIdx.x * 32, kt = blockIdx.y * 32;
    int tx = threadIdx.x, ty = threadIdx.y;   // block (32, 8)
#pragma unroll
    for (int r = 0; r < 4; r++) {
        int kl = ty + r * 8;
        ts[kl][tx] = __float2bfloat16(Wd[(kt + kl) * VV + nt + tx]);
    }
    __syncthreads();
#pragma unroll
    for (int r = 0; r < 4; r++) {
        int nl = ty + r * 8;
        g_WdT[(nt + nl) * 128 + kt + tx] = ts[tx][nl];
    }
}

__global__ void k_zero() {
    int i = blockIdx.x * 256 + threadIdx.x;
    if (i < NROWS) g_S[i] = 0.f;
}

__global__ void k_inv() {
    int i = blockIdx.x * 256 + threadIdx.x;
    if (i < NROWS) g_S[i] = 1.0f / g_S[i];
}

// ---------------- xz = emb[tok] @ Wx + b : [4096, 256] ----------------
__global__ __launch_bounds__(256) void k_embed(const int* __restrict__ tok,
                                               const float* __restrict__ emb,
                                               const float* __restrict__ Wx,
                                               const float* __restrict__ bias) {
    __shared__ float xs[64][36];   // [k_local][row], padded stride 36
    __shared__ int toks[32];
    int tid = threadIdx.x;
    int row0 = blockIdx.x * 32;
    if (tid < 32) toks[tid] = tok[row0 + tid];
    int jc = (tid & 63) * 4;       // 4 output cols
    int rb = (tid >> 6) * 8;       // 8 output rows
    float acc[8][4];
    float4 bv = *(const float4*)&bias[jc];
#pragma unroll
    for (int r = 0; r < 8; r++) { acc[r][0] = bv.x; acc[r][1] = bv.y; acc[r][2] = bv.z; acc[r][3] = bv.w; }
    for (int kc = 0; kc < 8; kc++) {
        __syncthreads();
#pragma unroll
        for (int i = 0; i < 8; i++) {
            int e = tid + i * 256; int r = e >> 6; int kk = e & 63;
            xs[kk][r] = emb[(long long)toks[r] * EE + kc * 64 + kk];
        }
        __syncthreads();
#pragma unroll 8
        for (int kk = 0; kk < 64; kk++) {
            float4 w  = *(const float4*)&Wx[(kc * 64 + kk) * 256 + jc];
            float4 x0 = *(const float4*)&xs[kk][rb];
            float4 x1 = *(const float4*)&xs[kk][rb + 4];
            float xv[8] = {x0.x, x0.y, x0.z, x0.w, x1.x, x1.y, x1.z, x1.w};
#pragma unroll
            for (int r = 0; r < 8; r++) {
                acc[r][0] += xv[r] * w.x; acc[r][1] += xv[r] * w.y;
                acc[r][2] += xv[r] * w.z; acc[r][3] += xv[r] * w.w;
            }
        }
    }
#pragma unroll
    for (int r = 0; r < 8; r++)
        *(float4*)&g_xz[(row0 + rb + r) * 256 + jc] = *(float4*)acc[r];
}

// ---------------- LSTM scan: 32 CTAs (one per batch), serial over T ----------------
__global__ __launch_bounds__(256) void k_lstm(const float* __restrict__ h0,
                                              const float* __restrict__ c0,
                                              const float* __restrict__ Wh,
                                              float* __restrict__ out) {
    int b = blockIdx.x, j = threadIdx.x;
    float wh[64];
#pragma unroll
    for (int k = 0; k < 64; k++) wh[k] = Wh[k * 256 + j];
    __shared__ __align__(16) float hsh[64];
    __shared__ float zb[256];
    if (j < 64) hsh[j] = h0[b * 64 + j];
    float creg = (j < 64) ? c0[b * 64 + j] : 0.f;
    const float* xzp = &g_xz[b * TT * 256 + j];
    float xv = xzp[0];
    __syncthreads();
    for (int t = 0; t < TT; t++) {
        float xnext = (t + 1 < TT) ? xzp[(t + 1) * 256] : 0.f;
        float s[4] = {0.f, 0.f, 0.f, 0.f};
#pragma unroll
        for (int c = 0; c < 4; c++) {
#pragma unroll
            for (int q = 0; q < 4; q++) {
                float4 h4 = *(const float4*)&hsh[c * 16 + q * 4];
                s[c] += wh[c * 16 + q * 4 + 0] * h4.x + wh[c * 16 + q * 4 + 1] * h4.y
                      + wh[c * 16 + q * 4 + 2] * h4.z + wh[c * 16 + q * 4 + 3] * h4.w;
            }
        }
        zb[j] = xv + (s[0] + s[1]) + (s[2] + s[3]);
        __syncthreads();
        if (j < 64) {
            float iv = sigmoid_ap(zb[j]);
            float fv = sigmoid_ap(zb[64 + j]);
            float gv = tanh_ap(zb[128 + j]);
            float ov = sigmoid_ap(zb[192 + j]);
            creg = fv * creg + iv * gv;
            float hn = ov * tanh_ap(creg);
            hsh[j] = hn;
            g_seq[(b * TT + t) * UU + j] = hn;
        }
        xv = xnext;
        __syncthreads();
    }
    if (j < 64) {
        out[OUT_SOFT + b * 64 + j] = hsh[j];          // hT
        out[OUT_SOFT + 2048 + b * 64 + j] = creg;     // cT
    }
}

// ---------------- attention + feat(bf16) ----------------
__global__ __launch_bounds__(128) void k_attn(const float* __restrict__ enc,
                                              const float* __restrict__ h0) {
    int t = blockIdx.x, b = blockIdx.y;
    int s = threadIdx.x;
    __shared__ __align__(16) float kv[64];
    __shared__ float pr[128];
    __shared__ float wred[4];
    if (s < 64) kv[s] = (t == 0) ? h0[b * 64 + s] : g_seq[(b * TT + t - 1) * UU + s];
    __syncthreads();
    const float* encb = enc + (long long)b * TT * UU;
    float sc = 0.f;
#pragma unroll
    for (int u4 = 0; u4 < 16; u4++) {
        float4 e4 = *(const float4*)&encb[s * UU + u4 * 4];
        float4 k4 = *(const float4*)&kv[u4 * 4];
        sc += e4.x * k4.x + e4.y * k4.y + e4.z * k4.z + e4.w * k4.w;
    }
    float m = sc;
#pragma unroll
    for (int o = 16; o > 0; o >>= 1) m = fmaxf(m, __shfl_xor_sync(0xffffffffu, m, o));
    if ((s & 31) == 0) wred[s >> 5] = m;
    __syncthreads();
    m = fmaxf(fmaxf(wred[0], wred[1]), fmaxf(wred[2], wred[3]));
    float ev = __expf(sc - m);
    float sm = ev;
#pragma unroll
    for (int o = 16; o > 0; o >>= 1) sm += __shfl_xor_sync(0xffffffffu, sm, o);
    __syncthreads();
    if ((s & 31) == 0) wred[s >> 5] = sm;
    __syncthreads();
    sm = wred[0] + wred[1] + wred[2] + wred[3];
    pr[s] = ev / sm;
    __syncthreads();
    if (s < 64) {
        float cx = 0.f;
#pragma unroll 8
        for (int q = 0; q < 128; q++) cx += pr[q] * encb[q * UU + s];
        int row = b * TT + t;
        g_feat[row * 128 + 64 + s] = __float2bfloat16(cx);
        g_feat[row * 128 + s]      = __float2bfloat16(g_seq[row * UU + s]);
    }
}

// ---------------- big GEMM pass A: exp(logits) -> g_E (fp16), S += sums ----------------
#define SMEM_GEMM (2 * 128 * 136 * 2 + 128 * 4)   // 70144 bytes

__global__ __launch_bounds__(256, 2) void k_gemm(const float* __restrict__ bd) {
    extern __shared__ __align__(16) char smem_raw[];
    __nv_bfloat16* Bs = (__nv_bfloat16*)smem_raw;       // [128 n][136 k]
    __nv_bfloat16* As = Bs + 128 * 136;                 // [128 m][136 k]
    float* bds = (float*)(As + 128 * 136);
    int tid = threadIdx.x;
    int nb = blockIdx.x * 128;

    // B tile resident across all M-tiles
#pragma unroll
    for (int i = 0; i < 8; i++) {
        int ch = tid + i * 256; int r = ch >> 4; int kc = (ch & 15) * 8;
        *(uint4*)&Bs[r * 136 + kc] = *(const uint4*)&g_WdT[(nb + r) * 128 + kc];
    }
    if (tid < 128) bds[tid] = bd[nb + tid];

    int w = tid >> 5, lane = tid & 31;
    int wm = (w & 3) * 32, wn = (w >> 2) * 64;
    int g = lane >> 2, qt = lane & 3;

    for (int mt = 0; mt < 32; mt++) {
        int mb = mt * 128;
        __syncthreads();
#pragma unroll
        for (int i = 0; i < 8; i++) {
            int ch = tid + i * 256; int r = ch >> 4; int kc = (ch & 15) * 8;
            *(uint4*)&As[r * 136 + kc] = *(const uint4*)&g_feat[(mb + r) * 128 + kc];
        }
        __syncthreads();

        float acc[2][8][4];
#pragma unroll
        for (int mf = 0; mf < 2; mf++)
#pragma unroll
            for (int nf = 0; nf < 8; nf++)
#pragma unroll
                for (int q = 0; q < 4; q++) acc[mf][nf][q] = 0.f;

#pragma unroll
        for (int ks = 0; ks < 8; ks++) {
            int kk = ks * 16 + qt * 2;
            unsigned a[2][4];
#pragma unroll
            for (int mf = 0; mf < 2; mf++) {
                int rr = wm + mf * 16 + g;
                a[mf][0] = *(const unsigned*)&As[rr * 136 + kk];
                a[mf][1] = *(const unsigned*)&As[(rr + 8) * 136 + kk];
                a[mf][2] = *(const unsigned*)&As[rr * 136 + kk + 8];
                a[mf][3] = *(const unsigned*)&As[(rr + 8) * 136 + kk + 8];
            }
#pragma unroll
            for (int nf = 0; nf < 8; nf++) {
                int cc = wn + nf * 8 + g;
                unsigned b0 = *(const unsigned*)&Bs[cc * 136 + kk];
                unsigned b1 = *(const unsigned*)&Bs[cc * 136 + kk + 8];
#pragma unroll
                for (int mf = 0; mf < 2; mf++) {
                    asm volatile(
                        "mma.sync.aligned.m16n8k16.row.col.f32.bf16.bf16.f32 "
                        "{%0,%1,%2,%3}, {%4,%5,%6,%7}, {%8,%9}, {%0,%1,%2,%3};\n"
                        : "+f"(acc[mf][nf][0]), "+f"(acc[mf][nf][1]),
                          "+f"(acc[mf][nf][2]), "+f"(acc[mf][nf][3])
                        : "r"(a[mf][0]), "r"(a[mf][1]), "r"(a[mf][2]), "r"(a[mf][3]),
                          "r"(b0), "r"(b1));
                }
            }
        }

#pragma unroll
        for (int mf = 0; mf < 2; mf++) {
            int r0 = wm + mf * 16 + g;
            long long ro0 = (long long)(mb + r0) * VV + nb;
            long long ro1 = (long long)(mb + r0 + 8) * VV + nb;
            float rs0 = 0.f, rs1 = 0.f;
#pragma unroll
            for (int nf = 0; nf < 8; nf++) {
                int c0 = wn + nf * 8 + qt * 2;
                float bd0 = bds[c0], bd1 = bds[c0 + 1];
                float e00 = __expf(acc[mf][nf][0] + bd0);
                float e01 = __expf(acc[mf][nf][1] + bd1);
                float e10 = __expf(acc[mf][nf][2] + bd0);
                float e11 = __expf(acc[mf][nf][3] + bd1);
                rs0 += e00 + e01;
                rs1 += e10 + e11;
                *(__half2*)&g_E[ro0 + c0] = __floats2half2_rn(e00, e01);
                *(__half2*)&g_E[ro1 + c0] = __floats2half2_rn(e10, e11);
            }
            rs0 += __shfl_xor_sync(0xffffffffu, rs0, 1);
            rs0 += __shfl_xor_sync(0xffffffffu, rs0, 2);
            rs1 += __shfl_xor_sync(0xffffffffu, rs1, 1);
            rs1 += __shfl_xor_sync(0xffffffffu, rs1, 2);
            if (qt == 0) {
                atomicAdd(&g_S[mb + r0], rs0);
                atomicAdd(&g_S[mb + r0 + 8], rs1);
            }
        }
    }
}

// ---------------- pass B: out = fp16_exp * invS (pure memory) ----------------
__global__ __launch_bounds__(256) void k_scale(float* __restrict__ out) {
    long long i4 = (long long)blockIdx.x * 256 + threadIdx.x;  // unit = 4 elems
    int row = (int)(i4 / (VV / 4));
    float is = g_S[row];                       // holds 1/S after k_inv
    uint2 raw = ((const uint2*)g_E)[i4];
    __half2 h0 = *(__half2*)&raw.x;
    __half2 h1 = *(__half2*)&raw.y;
    float2 f0 = __half22float2(h0);
    float2 f1 = __half22float2(h1);
    float4 v;
    v.x = f0.x * is; v.y = f0.y * is; v.z = f1.x * is; v.w = f1.y * is;
    *(float4*)&out[i4 * 4] = v;
}

// ---------------- launch ----------------
extern "C" void kernel_launch(void* const* d_in, const int* in_sizes, int n_in,
                              void* d_out, int out_size) {
    (void)in_sizes; (void)n_in; (void)out_size;
    const float* enc  = (const float*)d_in[0];
    const int*   dec  = (const int*)d_in[1];
    const float* h0   = (const float*)d_in[2];
    const float* c0   = (const float*)d_in[3];
    const float* emb  = (const float*)d_in[4];
    const float* Wx   = (const float*)d_in[5];
    const float* Wh   = (const float*)d_in[6];
    const float* bias = (const float*)d_in[7];
    const float* Wd   = (const float*)d_in[8];
    const float* bd   = (const float*)d_in[9];
    float* out = (float*)d_out;

    cudaFuncSetAttribute(k_gemm, cudaFuncAttributeMaxDynamicSharedMemorySize, SMEM_GEMM);

    k_wdt<<<dim3(1000, 4), dim3(32, 8)>>>(Wd);
    k_zero<<<16, 256>>>();
    k_embed<<<128, 256>>>(dec, emb, Wx, bias);
    k_lstm<<<32, 256>>>(h0, c0, Wh, out);
    k_attn<<<dim3(128, 32), 128>>>(enc, h0);
    k_gemm<<<250, 256, SMEM_GEMM>>>(bd);
    k_inv<<<16, 256>>>();
    k_scale<<<128000, 256>>>(out);
}

// round 4
// speedup vs baseline: 1.1018x; 1.0336x over previous
#include <cuda_runtime.h>
#include <cuda_bf16.h>
#include <cstdint>

#define BB 32
#define TT 128
#define UU 64
#define EE 512
#define VV 32000
#define NROWS (BB*TT)                 // 4096
#define OUT_SOFT 131072000LL          // NROWS * VV

// ---------------- device scratch ----------------
__device__ float g_xz[NROWS * 256];                         // 4 MB
__device__ float g_seq[NROWS * UU];                         // 1 MB
__device__ __align__(16) __nv_bfloat16 g_feat[NROWS * 128]; // 1 MB
__device__ __align__(16) __nv_bfloat16 g_WdT[VV * 128];     // 8 MB (Wd transposed, bf16)
__device__ float g_S[NROWS];                                // softmax denominators

__device__ __forceinline__ float tanh_ap(float x) {
    float y; asm("tanh.approx.f32 %0, %1;" : "=f"(y) : "f"(x)); return y;
}
__device__ __forceinline__ float sigmoid_ap(float x) {
    return 0.5f * tanh_ap(0.5f * x) + 0.5f;
}
__device__ __forceinline__ uint32_t smem_u32(const void* p) {
    uint32_t a;
    asm("{ .reg .u64 t; cvta.to.shared.u64 t, %1; cvt.u32.u64 %0, t; }" : "=r"(a) : "l"(p));
    return a;
}
#define CP_ASYNC16(dst, src) \
    asm volatile("cp.async.cg.shared.global [%0], [%1], 16;" :: "r"(dst), "l"(src) : "memory")
#define CP_COMMIT() asm volatile("cp.async.commit_group;" ::: "memory")
#define CP_WAIT0()  asm volatile("cp.async.wait_group 0;" ::: "memory")

// ---------------- Wd [128, 32000] f32 -> WdT [32000, 128] bf16 ----------------
__global__ void k_wdt(const float* __restrict__ Wd) {
    __shared__ __nv_bfloat16 ts[32][33];
    int nt = blockIdx.x * 32, kt = blockIdx.y * 32;
    int tx = threadIdx.x, ty = threadIdx.y;   // block (32, 8)
#pragma unroll
    for (int r = 0; r < 4; r++) {
        int kl = ty + r * 8;
        ts[kl][tx] = __float2bfloat16(Wd[(kt + kl) * VV + nt + tx]);
    }
    __syncthreads();
#pragma unroll
    for (int r = 0; r < 4; r++) {
        int nl = ty + r * 8;
        g_WdT[(nt + nl) * 128 + kt + tx] = ts[tx][nl];
    }
}

__global__ void k_zero() {
    int i = blockIdx.x * 256 + threadIdx.x;
    if (i < NROWS) g_S[i] = 0.f;
}
__global__ void k_inv() {
    int i = blockIdx.x * 256 + threadIdx.x;
    if (i < NROWS) g_S[i] = 1.0f / g_S[i];
}

// ---------------- xz = emb[tok] @ Wx + b : [4096, 256] ----------------
__global__ __launch_bounds__(256) void k_embed(const int* __restrict__ tok,
                                               const float* __restrict__ emb,
                                               const float* __restrict__ Wx,
                                               const float* __restrict__ bias) {
    __shared__ float xs[64][36];
    __shared__ int toks[32];
    int tid = threadIdx.x;
    int row0 = blockIdx.x * 32;
    if (tid < 32) toks[tid] = tok[row0 + tid];
    int jc = (tid & 63) * 4;
    int rb = (tid >> 6) * 8;
    float acc[8][4];
    float4 bv = *(const float4*)&bias[jc];
#pragma unroll
    for (int r = 0; r < 8; r++) { acc[r][0] = bv.x; acc[r][1] = bv.y; acc[r][2] = bv.z; acc[r][3] = bv.w; }
    for (int kc = 0; kc < 8; kc++) {
        __syncthreads();
#pragma unroll
        for (int i = 0; i < 8; i++) {
            int e = tid + i * 256; int r = e >> 6; int kk = e & 63;
            xs[kk][r] = emb[(long long)toks[r] * EE + kc * 64 + kk];
        }
        __syncthreads();
#pragma unroll 8
        for (int kk = 0; kk < 64; kk++) {
            float4 w  = *(const float4*)&Wx[(kc * 64 + kk) * 256 + jc];
            float4 x0 = *(const float4*)&xs[kk][rb];
            float4 x1 = *(const float4*)&xs[kk][rb + 4];
            float xv[8] = {x0.x, x0.y, x0.z, x0.w, x1.x, x1.y, x1.z, x1.w};
#pragma unroll
            for (int r = 0; r < 8; r++) {
                acc[r][0] += xv[r] * w.x; acc[r][1] += xv[r] * w.y;
                acc[r][2] += xv[r] * w.z; acc[r][3] += xv[r] * w.w;
            }
        }
    }
#pragma unroll
    for (int r = 0; r < 8; r++)
        *(float4*)&g_xz[(row0 + rb + r) * 256 + jc] = *(float4*)acc[r];
}

// ---------------- LSTM scan: 32 CTAs x 128 threads; thread j owns z[j], z[128+j] ----------------
__global__ __launch_bounds__(128) void k_lstm(const float* __restrict__ h0,
                                              const float* __restrict__ c0,
                                              const float* __restrict__ Wh,
                                              float* __restrict__ out) {
    int b = blockIdx.x, j = threadIdx.x;     // j in [0,128)
    float wh0[64], wh1[64];
#pragma unroll
    for (int k = 0; k < 64; k++) {
        wh0[k] = Wh[k * 256 + j];
        wh1[k] = Wh[k * 256 + 128 + j];
    }
    __shared__ __align__(16) float hsh[64];
    __shared__ float zb[256];
    if (j < 64) hsh[j] = h0[b * 64 + j];
    float creg = (j < 64) ? c0[b * 64 + j] : 0.f;
    const float* xzp = &g_xz[b * TT * 256];
    float xv0 = xzp[j], xv1 = xzp[128 + j];
    __syncthreads();
    for (int t = 0; t < TT; t++) {
        float xn0 = 0.f, xn1 = 0.f;
        if (t + 1 < TT) { xn0 = xzp[(t + 1) * 256 + j]; xn1 = xzp[(t + 1) * 256 + 128 + j]; }
        float s0a = 0.f, s0b = 0.f, s1a = 0.f, s1b = 0.f;
#pragma unroll
        for (int q = 0; q < 16; q += 2) {
            float4 ha = *(const float4*)&hsh[q * 4];
            float4 hb = *(const float4*)&hsh[q * 4 + 4];
            s0a += wh0[q*4+0]*ha.x + wh0[q*4+1]*ha.y + wh0[q*4+2]*ha.z + wh0[q*4+3]*ha.w;
            s1a += wh1[q*4+0]*ha.x + wh1[q*4+1]*ha.y + wh1[q*4+2]*ha.z + wh1[q*4+3]*ha.w;
            s0b += wh0[q*4+4]*hb.x + wh0[q*4+5]*hb.y + wh0[q*4+6]*hb.z + wh0[q*4+7]*hb.w;
            s1b += wh1[q*4+4]*hb.x + wh1[q*4+5]*hb.y + wh1[q*4+6]*hb.z + wh1[q*4+7]*hb.w;
        }
        zb[j] = xv0 + s0a + s0b;
        zb[128 + j] = xv1 + s1a + s1b;
        __syncthreads();
        if (j < 64) {
            float iv = sigmoid_ap(zb[j]);
            float fv = sigmoid_ap(zb[64 + j]);
            float gv = tanh_ap(zb[128 + j]);
            float ov = sigmoid_ap(zb[192 + j]);
            creg = fv * creg + iv * gv;
            float hn = ov * tanh_ap(creg);
            hsh[j] = hn;
            g_seq[(b * TT + t) * UU + j] = hn;
        }
        xv0 = xn0; xv1 = xn1;
        __syncthreads();
    }
    if (j < 64) {
        out[OUT_SOFT + b * 64 + j] = hsh[j];
        out[OUT_SOFT + 2048 + b * 64 + j] = creg;
    }
}

// ---------------- attention + feat(bf16) ----------------
__global__ __launch_bounds__(128) void k_attn(const float* __restrict__ enc,
                                              const float* __restrict__ h0) {
    int t = blockIdx.x, b = blockIdx.y;
    int s = threadIdx.x;
    __shared__ __align__(16) float kv[64];
    __shared__ float pr[128];
    __shared__ float wred[4];
    if (s < 64) kv[s] = (t == 0) ? h0[b * 64 + s] : g_seq[(b * TT + t - 1) * UU + s];
    __syncthreads();
    const float* encb = enc + (long long)b * TT * UU;
    float sc = 0.f;
#pragma unroll
    for (int u4 = 0; u4 < 16; u4++) {
        float4 e4 = *(const float4*)&encb[s * UU + u4 * 4];
        float4 k4 = *(const float4*)&kv[u4 * 4];
        sc += e4.x * k4.x + e4.y * k4.y + e4.z * k4.z + e4.w * k4.w;
    }
    float m = sc;
#pragma unroll
    for (int o = 16; o > 0; o >>= 1) m = fmaxf(m, __shfl_xor_sync(0xffffffffu, m, o));
    if ((s & 31) == 0) wred[s >> 5] = m;
    __syncthreads();
    m = fmaxf(fmaxf(wred[0], wred[1]), fmaxf(wred[2], wred[3]));
    float ev = __expf(sc - m);
    float sm = ev;
#pragma unroll
    for (int o = 16; o > 0; o >>= 1) sm += __shfl_xor_sync(0xffffffffu, sm, o);
    __syncthreads();
    if ((s & 31) == 0) wred[s >> 5] = sm;
    __syncthreads();
    sm = wred[0] + wred[1] + wred[2] + wred[3];
    pr[s] = ev / sm;
    __syncthreads();
    if (s < 64) {
        float cx = 0.f;
#pragma unroll 8
        for (int q = 0; q < 128; q++) cx += pr[q] * encb[q * UU + s];
        int row = b * TT + t;
        g_feat[row * 128 + 64 + s] = __float2bfloat16(cx);
        g_feat[row * 128 + s]      = __float2bfloat16(g_seq[row * UU + s]);
    }
}

// ---------------- big GEMM: logits = feat[4096,128] @ WdT^T + bd ----------------
// 4 warps, 64x64 warp tiles, CTA tile 128(M) x 128(N), A double-buffered cp.async.
// Pass A (WRITE=0): S[row] += sum(exp(z)); Pass B (WRITE=1): out = exp(z)*invS.
#define SMEM_GEMM (3 * 128 * 136 * 2 + 512)   // Bs + As0 + As1 + bds = 104960

template <int WRITE>
__global__ __launch_bounds__(128, 2) void k_gemm(const float* __restrict__ bd,
                                                 float* __restrict__ out) {
    extern __shared__ __align__(16) char smem_raw[];
    __nv_bfloat16* Bs  = (__nv_bfloat16*)smem_raw;          // [128 n][136 k]
    __nv_bfloat16* As0 = Bs + 128 * 136;
    __nv_bfloat16* As1 = As0 + 128 * 136;
    float* bds = (float*)(As1 + 128 * 136);
    uint32_t sb = smem_u32(smem_raw);
    uint32_t sA0 = sb + 128 * 136 * 2, sA1 = sb + 2 * 128 * 136 * 2;

    int tid = threadIdx.x;
    int w = tid >> 5, lane = tid & 31;
    int wm = (w & 1) * 64, wn = (w >> 1) * 64;
    int g = lane >> 2, qt = lane & 3;
    int nb = blockIdx.x * 128;

    // resident B tile + bias
#pragma unroll
    for (int i = 0; i < 16; i++) {
        int ch = i * 128 + tid; int r = ch >> 4; int kc = (ch & 15) * 8;
        *(uint4*)&Bs[r * 136 + kc] = *(const uint4*)&g_WdT[(nb + r) * 128 + kc];
    }
    bds[tid] = bd[nb + tid];

    // preload A tile 0
#pragma unroll
    for (int i = 0; i < 16; i++) {
        int ch = i * 128 + tid; int r = ch >> 4; int kc = (ch & 15) * 8;
        CP_ASYNC16(sA0 + (r * 136 + kc) * 2, (const char*)&g_feat[r * 128 + kc]);
    }
    CP_COMMIT();
    CP_WAIT0();
    __syncthreads();

    for (int mt = 0; mt < 32; mt++) {
        // prefetch next A tile into other buffer (overlaps compute+epilogue)
        if (mt + 1 < 32) {
            uint32_t dst = ((mt + 1) & 1) ? sA1 : sA0;
            const __nv_bfloat16* src = g_feat + (size_t)(mt + 1) * 128 * 128;
#pragma unroll
            for (int i = 0; i < 16; i++) {
                int ch = i * 128 + tid; int r = ch >> 4; int kc = (ch & 15) * 8;
                CP_ASYNC16(dst + (r * 136 + kc) * 2, (const char*)&src[r * 128 + kc]);
            }
            CP_COMMIT();
        }
        const __nv_bfloat16* As = (mt & 1) ? As1 : As0;

        float acc[4][8][4];
#pragma unroll
        for (int mf = 0; mf < 4; mf++)
#pragma unroll
            for (int nf = 0; nf < 8; nf++)
#pragma unroll
                for (int q = 0; q < 4; q++) acc[mf][nf][q] = 0.f;

#pragma unroll
        for (int ks = 0; ks < 8; ks++) {
            int kk = ks * 16 + qt * 2;
            unsigned a[4][4];
#pragma unroll
            for (int mf = 0; mf < 4; mf++) {
                int rr = wm + mf * 16 + g;
                a[mf][0] = *(const unsigned*)&As[rr * 136 + kk];
                a[mf][1] = *(const unsigned*)&As[(rr + 8) * 136 + kk];
                a[mf][2] = *(const unsigned*)&As[rr * 136 + kk + 8];
                a[mf][3] = *(const unsigned*)&As[(rr + 8) * 136 + kk + 8];
            }
#pragma unroll
            for (int nf = 0; nf < 8; nf++) {
                int cc = wn + nf * 8 + g;
                unsigned b0 = *(const unsigned*)&Bs[cc * 136 + kk];
                unsigned b1 = *(const unsigned*)&Bs[cc * 136 + kk + 8];
#pragma unroll
                for (int mf = 0; mf < 4; mf++) {
                    asm volatile(
                        "mma.sync.aligned.m16n8k16.row.col.f32.bf16.bf16.f32 "
                        "{%0,%1,%2,%3}, {%4,%5,%6,%7}, {%8,%9}, {%0,%1,%2,%3};\n"
                        : "+f"(acc[mf][nf][0]), "+f"(acc[mf][nf][1]),
                          "+f"(acc[mf][nf][2]), "+f"(acc[mf][nf][3])
                        : "r"(a[mf][0]), "r"(a[mf][1]), "r"(a[mf][2]), "r"(a[mf][3]),
                          "r"(b0), "r"(b1));
                }
            }
        }

#pragma unroll
        for (int mf = 0; mf < 4; mf++) {
            int r0 = wm + mf * 16 + g;
            int row = mt * 128 + r0;
            if (WRITE) {
                float is0 = g_S[row];          // holds 1/S after k_inv
                float is1 = g_S[row + 8];
                long long ro0 = (long long)row * VV + nb + wn;
                long long ro1 = ro0 + 8LL * VV;
#pragma unroll
                for (int nf = 0; nf < 8; nf++) {
                    int c0 = nf * 8 + qt * 2;
                    float bd0 = bds[wn + c0], bd1 = bds[wn + c0 + 1];
                    float2 v0, v1;
                    v0.x = __expf(acc[mf][nf][0] + bd0) * is0;
                    v0.y = __expf(acc[mf][nf][1] + bd1) * is0;
                    v1.x = __expf(acc[mf][nf][2] + bd0) * is1;
                    v1.y = __expf(acc[mf][nf][3] + bd1) * is1;
                    *(float2*)&out[ro0 + c0] = v0;
                    *(float2*)&out[ro1 + c0] = v1;
                }
            } else {
                float rs0 = 0.f, rs1 = 0.f;
#pragma unroll
                for (int nf = 0; nf < 8; nf++) {
                    int c0 = nf * 8 + qt * 2;
                    float bd0 = bds[wn + c0], bd1 = bds[wn + c0 + 1];
                    rs0 += __expf(acc[mf][nf][0] + bd0) + __expf(acc[mf][nf][1] + bd1);
                    rs1 += __expf(acc[mf][nf][2] + bd0) + __expf(acc[mf][nf][3] + bd1);
                }
                rs0 += __shfl_xor_sync(0xffffffffu, rs0, 1);
                rs0 += __shfl_xor_sync(0xffffffffu, rs0, 2);
                rs1 += __shfl_xor_sync(0xffffffffu, rs1, 1);
                rs1 += __shfl_xor_sync(0xffffffffu, rs1, 2);
                if (qt == 0) {
                    atomicAdd(&g_S[row], rs0);
                    atomicAdd(&g_S[row + 8], rs1);
                }
            }
        }

        if (mt + 1 < 32) CP_WAIT0();
        __syncthreads();
    }
}

// ---------------- launch ----------------
extern "C" void kernel_launch(void* const* d_in, const int* in_sizes, int n_in,
                              void* d_out, int out_size) {
    (void)in_sizes; (void)n_in; (void)out_size;
    const float* enc  = (const float*)d_in[0];
    const int*   dec  = (const int*)d_in[1];
    const float* h0   = (const float*)d_in[2];
    const float* c0   = (const float*)d_in[3];
    const float* emb  = (const float*)d_in[4];
    const float* Wx   = (const float*)d_in[5];
    const float* Wh   = (const float*)d_in[6];
    const float* bias = (const float*)d_in[7];
    const float* Wd   = (const float*)d_in[8];
    const float* bd   = (const float*)d_in[9];
    float* out = (float*)d_out;

    cudaFuncSetAttribute(k_gemm<0>, cudaFuncAttributeMaxDynamicSharedMemorySize, SMEM_GEMM);
    cudaFuncSetAttribute(k_gemm<1>, cudaFuncAttributeMaxDynamicSharedMemorySize, SMEM_GEMM);

    k_wdt<<<dim3(1000, 4), dim3(32, 8)>>>(Wd);
    k_zero<<<16, 256>>>();
    k_embed<<<128, 256>>>(dec, emb, Wx, bias);
    k_lstm<<<32, 128>>>(h0, c0, Wh, out);
    k_attn<<<dim3(128, 32), 128>>>(enc, h0);
    k_gemm<0><<<250, 128, SMEM_GEMM>>>(bd, out);
    k_inv<<<16, 256>>>();
    k_gemm<1><<<250, 128, SMEM_GEMM>>>(bd, out);
}

// round 6
// speedup vs baseline: 1.1368x; 1.0318x over previous
#include <cuda_runtime.h>
#include <cuda_bf16.h>
#include <cstdint>

#define BB 32
#define TT 128
#define UU 64
#define EE 512
#define VV 32000
#define NROWS (BB*TT)                 // 4096
#define OUT_SOFT 131072000LL          // NROWS * VV

// ---------------- device scratch ----------------
__device__ float g_xz[NROWS * 256];                         // 4 MB
__device__ float g_seq[NROWS * UU];                         // 1 MB
__device__ __align__(16) __nv_bfloat16 g_feat[NROWS * 128]; // 1 MB
__device__ __align__(16) __nv_bfloat16 g_WdT[VV * 128];     // 8 MB (Wd transposed, bf16)
__device__ float g_S[NROWS];                                // softmax denominators

__device__ __forceinline__ float tanh_ap(float x) {
    float y; asm("tanh.approx.f32 %0, %1;" : "=f"(y) : "f"(x)); return y;
}
__device__ __forceinline__ float sigmoid_ap(float x) {
    return 0.5f * tanh_ap(0.5f * x) + 0.5f;
}
__device__ __forceinline__ uint32_t smem_u32(const void* p) {
    uint32_t a;
    asm("{ .reg .u64 t; cvta.to.shared.u64 t, %1; cvt.u32.u64 %0, t; }" : "=r"(a) : "l"(p));
    return a;
}
#define CP_ASYNC16(dst, src) \
    asm volatile("cp.async.cg.shared.global [%0], [%1], 16;" :: "r"(dst), "l"(src) : "memory")
#define CP_ASYNC4(dst, src) \
    asm volatile("cp.async.ca.shared.global [%0], [%1], 4;" :: "r"(dst), "l"(src) : "memory")
#define CP_COMMIT() asm volatile("cp.async.commit_group;" ::: "memory")
#define CP_WAIT0()  asm volatile("cp.async.wait_group 0;" ::: "memory")

// ---------------- Wd [128, 32000] f32 -> WdT [32000, 128] bf16 ----------------
__global__ void k_wdt(const float* __restrict__ Wd) {
    __shared__ __nv_bfloat16 ts[32][33];
    int nt = blockIdx.x * 32, kt = blockIdx.y * 32;
    int tx = threadIdx.x, ty = threadIdx.y;   // block (32, 8)
#pragma unroll
    for (int r = 0; r < 4; r++) {
        int kl = ty + r * 8;
        ts[kl][tx] = __float2bfloat16(Wd[(kt + kl) * VV + nt + tx]);
    }
    __syncthreads();
#pragma unroll
    for (int r = 0; r < 4; r++) {
        int nl = ty + r * 8;
        g_WdT[(nt + nl) * 128 + kt + tx] = ts[tx][nl];
    }
}

__global__ void k_zero() {
    int i = blockIdx.x * 256 + threadIdx.x;
    if (i < NROWS) g_S[i] = 0.f;
}
__global__ void k_inv() {
    int i = blockIdx.x * 256 + threadIdx.x;
    if (i < NROWS) g_S[i] = 1.0f / g_S[i];
}

// ---------------- xz = emb[tok] @ Wx + b : [4096, 256] ----------------
__global__ __launch_bounds__(256) void k_embed(const int* __restrict__ tok,
                                               const float* __restrict__ emb,
                                               const float* __restrict__ Wx,
                                               const float* __restrict__ bias) {
    __shared__ float xs[64][36];
    __shared__ int toks[32];
    int tid = threadIdx.x;
    int row0 = blockIdx.x * 32;
    if (tid < 32) toks[tid] = tok[row0 + tid];
    int jc = (tid & 63) * 4;
    int rb = (tid >> 6) * 8;
    float acc[8][4];
    float4 bv = *(const float4*)&bias[jc];
#pragma unroll
    for (int r = 0; r < 8; r++) { acc[r][0] = bv.x; acc[r][1] = bv.y; acc[r][2] = bv.z; acc[r][3] = bv.w; }
    for (int kc = 0; kc < 8; kc++) {
        __syncthreads();
#pragma unroll
        for (int i = 0; i < 8; i++) {
            int e = tid + i * 256; int r = e >> 6; int kk = e & 63;
            xs[kk][r] = emb[(long long)toks[r] * EE + kc * 64 + kk];
        }
        __syncthreads();
#pragma unroll 8
        for (int kk = 0; kk < 64; kk++) {
            float4 w  = *(const float4*)&Wx[(kc * 64 + kk) * 256 + jc];
            float4 x0 = *(const float4*)&xs[kk][rb];
            float4 x1 = *(const float4*)&xs[kk][rb + 4];
            float xv[8] = {x0.x, x0.y, x0.z, x0.w, x1.x, x1.y, x1.z, x1.w};
#pragma unroll
            for (int r = 0; r < 8; r++) {
                acc[r][0] += xv[r] * w.x; acc[r][1] += xv[r] * w.y;
                acc[r][2] += xv[r] * w.z; acc[r][3] += xv[r] * w.w;
            }
        }
    }
#pragma unroll
    for (int r = 0; r < 8; r++)
        *(float4*)&g_xz[(row0 + rb + r) * 256 + jc] = *(float4*)acc[r];
}

// ---------------- LSTM scan: shuffle-gate layout, 1 barrier/step ----------------
// 256 threads: thread (j = tid>>2, gate = tid&3) computes z[gate*64+j].
// The 4 gate threads for a j are consecutive lanes -> shfl exchange, redundant gate math.
__global__ __launch_bounds__(256) void k_lstm(const float* __restrict__ h0,
                                              const float* __restrict__ c0,
                                              const float* __restrict__ Wh,
                                              float* __restrict__ out) {
    int b = blockIdx.x, tid = threadIdx.x;
    int j = tid >> 2, gate = tid & 3;
    int col = gate * 64 + j;
    float wh[64];
#pragma unroll
    for (int k = 0; k < 64; k++) wh[k] = Wh[k * 256 + col];
    __shared__ __align__(16) float hbuf[2][64];
    if (tid < 64) hbuf[0][tid] = h0[b * 64 + tid];
    float creg = c0[b * 64 + j];
    const float* xzp = &g_xz[b * TT * 256];
    float xv = xzp[col];
    unsigned lb = tid & 28;            // (lane & ~3)
    __syncthreads();
    for (int t = 0; t < TT; t++) {
        float xn = (t + 1 < TT) ? xzp[(t + 1) * 256 + col] : 0.f;
        const float* h = hbuf[t & 1];
        float s0 = 0.f, s1 = 0.f, s2 = 0.f, s3 = 0.f;
#pragma unroll
        for (int q = 0; q < 16; q += 4) {
            float4 h4a = *(const float4*)&h[q * 4];
            float4 h4b = *(const float4*)&h[q * 4 + 4];
            float4 h4c = *(const float4*)&h[q * 4 + 8];
            float4 h4d = *(const float4*)&h[q * 4 + 12];
            s0 += wh[q*4+ 0]*h4a.x + wh[q*4+ 1]*h4a.y + wh[q*4+ 2]*h4a.z + wh[q*4+ 3]*h4a.w;
            s1 += wh[q*4+ 4]*h4b.x + wh[q*4+ 5]*h4b.y + wh[q*4+ 6]*h4b.z + wh[q*4+ 7]*h4b.w;
            s2 += wh[q*4+ 8]*h4c.x + wh[q*4+ 9]*h4c.y + wh[q*4+10]*h4c.z + wh[q*4+11]*h4c.w;
            s3 += wh[q*4+12]*h4d.x + wh[q*4+13]*h4d.y + wh[q*4+14]*h4d.z + wh[q*4+15]*h4d.w;
        }
        float z = xv + (s0 + s1) + (s2 + s3);
        float zi = __shfl_sync(0xffffffffu, z, lb | 0);
        float zf = __shfl_sync(0xffffffffu, z, lb | 1);
        float zg = __shfl_sync(0xffffffffu, z, lb | 2);
        float zo = __shfl_sync(0xffffffffu, z, lb | 3);
        float iv = sigmoid_ap(zi);
        float fv = sigmoid_ap(zf);
        float gv = tanh_ap(zg);
        float ov = sigmoid_ap(zo);
        creg = fv * creg + iv * gv;
        float hn = ov * tanh_ap(creg);
        if (gate == 0) {
            hbuf[(t + 1) & 1][j] = hn;
            g_seq[(b * TT + t) * UU + j] = hn;
        }
        xv = xn;
        __syncthreads();
    }
    if (tid < 64) out[OUT_SOFT + b * 64 + tid] = hbuf[0][tid];   // hT (after 128 steps buf 0)
    if (gate == 0) out[OUT_SOFT + 2048 + b * 64 + j] = creg;     // cT
}

// ---------------- attention + feat(bf16) ----------------
__global__ __launch_bounds__(128) void k_attn(const float* __restrict__ enc,
                                              const float* __restrict__ h0) {
    int t = blockIdx.x, b = blockIdx.y;
    int s = threadIdx.x;
    __shared__ __align__(16) float kv[64];
    __shared__ float pr[128];
    __shared__ float wred[4];
    if (s < 64) kv[s] = (t == 0) ? h0[b * 64 + s] : g_seq[(b * TT + t - 1) * UU + s];
    __syncthreads();
    const float* encb = enc + (long long)b * TT * UU;
    float sc = 0.f;
#pragma unroll
    for (int u4 = 0; u4 < 16; u4++) {
        float4 e4 = *(const float4*)&encb[s * UU + u4 * 4];
        float4 k4 = *(const float4*)&kv[u4 * 4];
        sc += e4.x * k4.x + e4.y * k4.y + e4.z * k4.z + e4.w * k4.w;
    }
    float m = sc;
#pragma unroll
    for (int o = 16; o > 0; o >>= 1) m = fmaxf(m, __shfl_xor_sync(0xffffffffu, m, o));
    if ((s & 31) == 0) wred[s >> 5] = m;
    __syncthreads();
    m = fmaxf(fmaxf(wred[0], wred[1]), fmaxf(wred[2], wred[3]));
    float ev = __expf(sc - m);
    float sm = ev;
#pragma unroll
    for (int o = 16; o > 0; o >>= 1) sm += __shfl_xor_sync(0xffffffffu, sm, o);
    __syncthreads();
    if ((s & 31) == 0) wred[s >> 5] = sm;
    __syncthreads();
    sm = wred[0] + wred[1] + wred[2] + wred[3];
    pr[s] = ev / sm;
    __syncthreads();
    if (s < 64) {
        float cx = 0.f;
#pragma unroll 8
        for (int q = 0; q < 128; q++) cx += pr[q] * encb[q * UU + s];
        int row = b * TT + t;
        g_feat[row * 128 + 64 + s] = __float2bfloat16(cx);
        g_feat[row * 128 + s]      = __float2bfloat16(g_seq[row * UU + s]);
    }
}

// ---------------- big GEMM: persistent, balanced ----------------
// 2000 items = 250 N-chunks (128 cols) x 8 M-segments (4 tiles of 128 rows).
// grid 296 (2 CTA/SM, all resident), items strided by gridDim.
// Pass A (WRITE=0): S[row] += sum(exp(z+bd)); Pass B: out = exp(z+bd)*invS.
#define SMEM_GEMM (3 * 128 * 136 * 2 + 512)   // Bs + As0 + As1 + bds
#define NITEMS 2000

template <int WRITE>
__global__ __launch_bounds__(128, 2) void k_gemm(const float* __restrict__ bd,
                                                 float* __restrict__ out) {
    extern __shared__ __align__(16) char smem_raw[];
    __nv_bfloat16* Bs  = (__nv_bfloat16*)smem_raw;          // [128 n][136 k]
    __nv_bfloat16* As0 = Bs + 128 * 136;
    __nv_bfloat16* As1 = As0 + 128 * 136;
    float* bds = (float*)(As1 + 128 * 136);
    uint32_t sb = smem_u32(smem_raw);
    uint32_t sB = sb, sA0 = sb + 128 * 136 * 2, sA1 = sb + 2 * 128 * 136 * 2;
    uint32_t sbd = sb + 3 * 128 * 136 * 2;

    int tid = threadIdx.x;
    int w = tid >> 5, lane = tid & 31;
    int wm = (w & 1) * 64, wn = (w >> 1) * 64;
    int g = lane >> 2, qt = lane & 3;

    for (int it = blockIdx.x; it < NITEMS; it += gridDim.x) {
        int nchunk = it >> 3, mseg = it & 7;
        int nb = nchunk * 128;
        int mt0 = mseg * 4;

        // B tile + bias + first A tile, all async
#pragma unroll
        for (int i = 0; i < 16; i++) {
            int ch = i * 128 + tid; int r = ch >> 4; int kc = (ch & 15) * 8;
            CP_ASYNC16(sB + (r * 136 + kc) * 2, (const char*)&g_WdT[(nb + r) * 128 + kc]);
        }
        CP_ASYNC4(sbd + tid * 4, (const char*)&bd[nb + tid]);
        {
            const __nv_bfloat16* src = g_feat + (size_t)mt0 * 128 * 128;
#pragma unroll
            for (int i = 0; i < 16; i++) {
                int ch = i * 128 + tid; int r = ch >> 4; int kc = (ch & 15) * 8;
                CP_ASYNC16(sA0 + (r * 136 + kc) * 2, (const char*)&src[r * 128 + kc]);
            }
        }
        CP_COMMIT();
        CP_WAIT0();
        __syncthreads();

#pragma unroll 1
        for (int i = 0; i < 4; i++) {
            int mt = mt0 + i;
            if (i < 3) {
                uint32_t dst = ((i + 1) & 1) ? sA1 : sA0;
                const __nv_bfloat16* src = g_feat + (size_t)(mt + 1) * 128 * 128;
#pragma unroll
                for (int q = 0; q < 16; q++) {
                    int ch = q * 128 + tid; int r = ch >> 4; int kc = (ch & 15) * 8;
                    CP_ASYNC16(dst + (r * 136 + kc) * 2, (const char*)&src[r * 128 + kc]);
                }
                CP_COMMIT();
            }
            const __nv_bfloat16* As = (i & 1) ? As1 : As0;

            float acc[4][8][4];
#pragma unroll
            for (int mf = 0; mf < 4; mf++)
#pragma unroll
                for (int nf = 0; nf < 8; nf++)
#pragma unroll
                    for (int q = 0; q < 4; q++) acc[mf][nf][q] = 0.f;

#pragma unroll
            for (int ks = 0; ks < 8; ks++) {
                int kk = ks * 16 + qt * 2;
                unsigned a[4][4];
#pragma unroll
                for (int mf = 0; mf < 4; mf++) {
                    int rr = wm + mf * 16 + g;
                    a[mf][0] = *(const unsigned*)&As[rr * 136 + kk];
                    a[mf][1] = *(const unsigned*)&As[(rr + 8) * 136 + kk];
                    a[mf][2] = *(const unsigned*)&As[rr * 136 + kk + 8];
                    a[mf][3] = *(const unsigned*)&As[(rr + 8) * 136 + kk + 8];
                }
#pragma unroll
                for (int nf = 0; nf < 8; nf++) {
                    int cc = wn + nf * 8 + g;
                    unsigned b0 = *(const unsigned*)&Bs[cc * 136 + kk];
                    unsigned b1 = *(const unsigned*)&Bs[cc * 136 + kk + 8];
#pragma unroll
                    for (int mf = 0; mf < 4; mf++) {
                        asm volatile(
                            "mma.sync.aligned.m16n8k16.row.col.f32.bf16.bf16.f32 "
                            "{%0,%1,%2,%3}, {%4,%5,%6,%7}, {%8,%9}, {%0,%1,%2,%3};\n"
                            : "+f"(acc[mf][nf][0]), "+f"(acc[mf][nf][1]),
                              "+f"(acc[mf][nf][2]), "+f"(acc[mf][nf][3])
                            : "r"(a[mf][0]), "r"(a[mf][1]), "r"(a[mf][2]), "r"(a[mf][3]),
                              "r"(b0), "r"(b1));
                    }
                }
            }

#pragma unroll
            for (int mf = 0; mf < 4; mf++) {
                int r0 = wm + mf * 16 + g;
                int row = mt * 128 + r0;
                if (WRITE) {
                    float is0 = g_S[row];          // holds 1/S after k_inv
                    float is1 = g_S[row + 8];
                    long long ro0 = (long long)row * VV + nb + wn;
                    long long ro1 = ro0 + 8LL * VV;
#pragma unroll
                    for (int nf = 0; nf < 8; nf++) {
                        int c0 = nf * 8 + qt * 2;
                        float bd0 = bds[wn + c0], bd1 = bds[wn + c0 + 1];
                        float2 v0, v1;
                        v0.x = __expf(acc[mf][nf][0] + bd0) * is0;
                        v0.y = __expf(acc[mf][nf][1] + bd1) * is0;
                        v1.x = __expf(acc[mf][nf][2] + bd0) * is1;
                        v1.y = __expf(acc[mf][nf][3] + bd1) * is1;
                        *(float2*)&out[ro0 + c0] = v0;
                        *(float2*)&out[ro1 + c0] = v1;
                    }
                } else {
                    float rs0 = 0.f, rs1 = 0.f;
#pragma unroll
                    for (int nf = 0; nf < 8; nf++) {
                        int c0 = nf * 8 + qt * 2;
                        float bd0 = bds[wn + c0], bd1 = bds[wn + c0 + 1];
                        rs0 += __expf(acc[mf][nf][0] + bd0) + __expf(acc[mf][nf][1] + bd1);
                        rs1 += __expf(acc[mf][nf][2] + bd0) + __expf(acc[mf][nf][3] + bd1);
                    }
                    rs0 += __shfl_xor_sync(0xffffffffu, rs0, 1);
                    rs0 += __shfl_xor_sync(0xffffffffu, rs0, 2);
                    rs1 += __shfl_xor_sync(0xffffffffu, rs1, 1);
                    rs1 += __shfl_xor_sync(0xffffffffu, rs1, 2);
                    if (qt == 0) {
                        atomicAdd(&g_S[row], rs0);
                        atomicAdd(&g_S[row + 8], rs1);
                    }
                }
            }

            if (i < 3) CP_WAIT0();
            __syncthreads();
        }
    }
}

// ---------------- launch ----------------
extern "C" void kernel_launch(void* const* d_in, const int* in_sizes, int n_in,
                              void* d_out, int out_size) {
    (void)in_sizes; (void)n_in; (void)out_size;
    const float* enc  = (const float*)d_in[0];
    const int*   dec  = (const int*)d_in[1];
    const float* h0   = (const float*)d_in[2];
    const float* c0   = (const float*)d_in[3];
    const float* emb  = (const float*)d_in[4];
    const float* Wx   = (const float*)d_in[5];
    const float* Wh   = (const float*)d_in[6];
    const float* bias = (const float*)d_in[7];
    const float* Wd   = (const float*)d_in[8];
    const float* bd   = (const float*)d_in[9];
    float* out = (float*)d_out;

    cudaFuncSetAttribute(k_gemm<0>, cudaFuncAttributeMaxDynamicSharedMemorySize, SMEM_GEMM);
    cudaFuncSetAttribute(k_gemm<1>, cudaFuncAttributeMaxDynamicSharedMemorySize, SMEM_GEMM);

    k_wdt<<<dim3(1000, 4), dim3(32, 8)>>>(Wd);
    k_zero<<<16, 256>>>();
    k_embed<<<128, 256>>>(dec, emb, Wx, bias);
    k_lstm<<<32, 256>>>(h0, c0, Wh, out);
    k_attn<<<dim3(128, 32), 128>>>(enc, h0);
    k_gemm<0><<<296, 128, SMEM_GEMM>>>(bd, out);
    k_inv<<<16, 256>>>();
    k_gemm<1><<<296, 128, SMEM_GEMM>>>(bd, out);
}